// round 12
// baseline (speedup 1.0000x reference)
#include <cuda_runtime.h>

// CumulantSOAP_CV: per-column mean & variance over X (200000 x 576 fp32),
// then project (cum - mu) @ W -> (1 x 4).
// pass1: R1 streaming loop + __ldcs (best measured) + in-block phase fold
//        (smem epilogue) -> partials shrink 4x to [296][576] (1.36 MB).
// tail:  74 blocks; stage A = ONE memory round-trip (2 independent float4
//        loads per thread), grid barrier, block 0 folds 74 rows + projects.

#define N_ROWS   200000
#define P        576
#define NBLK     296
#define RPB      ((N_ROWS + NBLK - 1) / NBLK)   // 676 rows per block
#define NPART    NBLK                            // 296 partial rows (post-fold)
#define NRED     74                              // tail stage-A blocks (one wave)
#define ROWS_PER_RED (NPART / NRED)              // 4

// Scratch (allocation-free __device__ globals).
__device__ float g_ps [NPART][P];   // partial sums      (0.68 MB)
__device__ float g_pq [NPART][P];   // partial sum-sqs   (0.68 MB)
__device__ float g_ps2[NRED][P];
__device__ float g_pq2[NRED][P];
__device__ int   g_cnt;             // zero-init; reset by block 0 each run

// ---------------------------------------------------------------------------
// Pass 1: streaming reduction over X. blockDim = 576, grid = 296 (2 CTA/SM).
// Loop identical to R11 (__ldcs). Epilogue: fold the 4 row-phases through
// smem, then 144 coalesced float4 stores per block.
// ---------------------------------------------------------------------------
__global__ __launch_bounds__(576) void pass1_kernel(const float* __restrict__ X) {
    const int b  = blockIdx.x;
    const int t  = threadIdx.x;
    const int c4 = t % 144;      // float4 column index (0..143)
    const int rs = t / 144;      // 0..3

    const int r0 = b * RPB;
    int r1 = r0 + RPB;
    if (r1 > N_ROWS) r1 = N_ROWS;

    const float4* __restrict__ Xv = reinterpret_cast<const float4*>(X);

    float4 s = make_float4(0.f, 0.f, 0.f, 0.f);
    float4 q = make_float4(0.f, 0.f, 0.f, 0.f);

    #pragma unroll 4
    for (int r = r0 + rs; r < r1; r += 4) {
        float4 x = __ldcs(&Xv[(size_t)r * 144 + c4]);
        s.x += x.x; s.y += x.y; s.z += x.z; s.w += x.w;
        q.x += x.x * x.x; q.y += x.y * x.y; q.z += x.z * x.z; q.w += x.w * x.w;
    }

    // Fold the 4 row-phases in shared memory (phases 1..3 park, phase 0 sums).
    __shared__ float4 sh_s[3][144];
    __shared__ float4 sh_q[3][144];
    if (rs > 0) { sh_s[rs - 1][c4] = s; sh_q[rs - 1][c4] = q; }
    __syncthreads();
    if (rs == 0) {
        #pragma unroll
        for (int ph = 0; ph < 3; ph++) {
            float4 a = sh_s[ph][c4];
            s.x += a.x; s.y += a.y; s.z += a.z; s.w += a.w;
            float4 e = sh_q[ph][c4];
            q.x += e.x; q.y += e.y; q.z += e.z; q.w += e.w;
        }
        reinterpret_cast<float4*>(&g_ps[b][0])[c4] = s;
        reinterpret_cast<float4*>(&g_pq[b][0])[c4] = q;
    }
}

// ---------------------------------------------------------------------------
// Tail kernel: 74 blocks x 576 threads. Thread layout (c4 = t%144, rs = t/144).
//  Stage A: block b covers rows [4b, 4b+4); phase rs takes row 4b+rs ->
//           exactly 2 INDEPENDENT float4 loads per thread (one per array):
//           a single memory round-trip. Phase-fold via smem, coalesced store.
//  Grid barrier over 74 co-resident blocks.
//  Stage B: block 0 folds the 74 rows of g_ps2/g_pq2 (phase-split), then
//           cumulants + projection + deterministic tree reduction.
// mom1 == 0 analytically (reference's fp32 residual ~1e-7 is negligible at
// the 1e-3 output tolerance).
// ---------------------------------------------------------------------------
__global__ __launch_bounds__(576) void tail_kernel(const float* __restrict__ mu,
                                                   const float* __restrict__ W,
                                                   float* __restrict__ out) {
    const int b  = blockIdx.x;    // 0..73
    const int t  = threadIdx.x;   // 0..575
    const int c4 = t % 144;
    const int rs = t / 144;       // 0..3

    __shared__ float4 park_s[3][144];
    __shared__ float4 park_q[3][144];

    // ---------------- Stage A: one round-trip fold of 4 rows --------------
    {
        const int row = b * ROWS_PER_RED + rs;
        float4 s = reinterpret_cast<const float4*>(&g_ps[row][0])[c4];
        float4 q = reinterpret_cast<const float4*>(&g_pq[row][0])[c4];

        if (rs > 0) { park_s[rs - 1][c4] = s; park_q[rs - 1][c4] = q; }
        __syncthreads();
        if (rs == 0) {
            #pragma unroll
            for (int ph = 0; ph < 3; ph++) {
                float4 a = park_s[ph][c4];
                s.x += a.x; s.y += a.y; s.z += a.z; s.w += a.w;
                float4 e = park_q[ph][c4];
                q.x += e.x; q.y += e.y; q.z += e.z; q.w += e.w;
            }
            reinterpret_cast<float4*>(&g_ps2[b][0])[c4] = s;
            reinterpret_cast<float4*>(&g_pq2[b][0])[c4] = q;
        }
    }

    // ---------------- Grid barrier over 74 blocks -------------------------
    __threadfence();
    __syncthreads();
    if (t == 0) atomicAdd(&g_cnt, 1);

    if (b != 0) return;

    if (t == 0) {
        while (*(volatile int*)&g_cnt < NRED) __nanosleep(32);
        __threadfence();              // acquire: all g_ps2/g_pq2 visible
    }
    __syncthreads();

    // ---------------- Stage B: fold 74 rows (float4, phase-split) ---------
    float4 s = make_float4(0.f, 0.f, 0.f, 0.f);
    float4 q = make_float4(0.f, 0.f, 0.f, 0.f);
    #pragma unroll 4
    for (int i = rs; i < NRED; i += 4) {
        float4 a = reinterpret_cast<const float4*>(&g_ps2[i][0])[c4];
        s.x += a.x; s.y += a.y; s.z += a.z; s.w += a.w;
        float4 e = reinterpret_cast<const float4*>(&g_pq2[i][0])[c4];
        q.x += e.x; q.y += e.y; q.z += e.z; q.w += e.w;
    }
    if (rs > 0) { park_s[rs - 1][c4] = s; park_q[rs - 1][c4] = q; }
    __syncthreads();

    __shared__ float4 tot_s[144];
    __shared__ float4 tot_q[144];
    if (rs == 0) {
        #pragma unroll
        for (int ph = 0; ph < 3; ph++) {
            float4 a = park_s[ph][c4];
            s.x += a.x; s.y += a.y; s.z += a.z; s.w += a.w;
            float4 e = park_q[ph][c4];
            q.x += e.x; q.y += e.y; q.z += e.z; q.w += e.w;
        }
        tot_s[c4] = s;
        tot_q[c4] = q;
    }
    __syncthreads();

    // ---------------- Cumulants + projection (thread t = column t) --------
    const float s2 = reinterpret_cast<const float*>(tot_s)[t];
    const float q2 = reinterpret_cast<const float*>(tot_q)[t];

    const float invN = 1.0f / (float)N_ROWS;
    const float m    = s2 * invN;
    const float mom2 = q2 * invN - m * m;

    const int j0 = 3 * t;
    const float d0 = m    - mu[j0 + 0];
    const float d1 = 0.f  - mu[j0 + 1];
    const float d2 = mom2 - mu[j0 + 2];

    float4 acc;
    acc.x = d0 * W[(j0 + 0) * 4 + 0] + d1 * W[(j0 + 1) * 4 + 0] + d2 * W[(j0 + 2) * 4 + 0];
    acc.y = d0 * W[(j0 + 0) * 4 + 1] + d1 * W[(j0 + 1) * 4 + 1] + d2 * W[(j0 + 2) * 4 + 1];
    acc.z = d0 * W[(j0 + 0) * 4 + 2] + d1 * W[(j0 + 1) * 4 + 2] + d2 * W[(j0 + 2) * 4 + 2];
    acc.w = d0 * W[(j0 + 0) * 4 + 3] + d1 * W[(j0 + 1) * 4 + 3] + d2 * W[(j0 + 2) * 4 + 3];

    __shared__ float4 sh3[576];
    sh3[t] = acc;
    __syncthreads();

    if (t < 64) {
        float4 a = sh3[t];
        for (int i = t + 64; i < 576; i += 64) {
            float4 bb = sh3[i];
            a.x += bb.x; a.y += bb.y; a.z += bb.z; a.w += bb.w;
        }
        sh3[t] = a;
    }
    __syncthreads();
    #pragma unroll
    for (int w = 32; w > 0; w >>= 1) {
        if (t < w) {
            float4 a = sh3[t], bb = sh3[t + w];
            a.x += bb.x; a.y += bb.y; a.z += bb.z; a.w += bb.w;
            sh3[t] = a;
        }
        __syncthreads();
    }

    if (t == 0) {
        out[0] = sh3[0].x;
        out[1] = sh3[0].y;
        out[2] = sh3[0].z;
        out[3] = sh3[0].w;
        g_cnt = 0;   // reset for next graph replay (all other blocks done)
    }
}

extern "C" void kernel_launch(void* const* d_in, const int* in_sizes, int n_in,
                              void* d_out, int out_size) {
    (void)in_sizes; (void)n_in; (void)out_size;
    const float* X  = (const float*)d_in[0];   // (200000, 576)
    const float* mu = (const float*)d_in[1];   // (1728,)
    const float* W  = (const float*)d_in[2];   // (1728, 4)
    float* out = (float*)d_out;                // (1, 4)

    pass1_kernel<<<NBLK, 576>>>(X);
    tail_kernel<<<NRED, 576>>>(mu, W, out);
}